// round 11
// baseline (speedup 1.0000x reference)
#include <cuda_runtime.h>
#include <cstdint>
#include <math.h>

#define Bb 16
#define Ff 128
#define Nn 2048
#define BN (Bb*Nn)          // 32768
#define TOT (Bb*Ff*Nn)      // 4194304
#define NBLK 512            // k_fused grid size

// scratch (allocation-free: __device__ globals)
__device__ float g_s[BN];
__device__ float g_psum[NBLK];
__device__ float g_psq[NBLK];

// ---------------------------------------------------------------------------
// Pass 1: s[b,n] = sum_f v[f]*emb[b,f,n]; per-block partial sum/sumsq.
// Proven-fastest structure (R7): 512 threads = 8 fc (16 f) x 64 n. Grid 512.
// ---------------------------------------------------------------------------
__global__ void __launch_bounds__(512) k_fused(const float* __restrict__ emb,
                                               const float* __restrict__ v) {
    __shared__ float sv[Ff];
    __shared__ float spart[512];
    __shared__ float red_sum[16];
    __shared__ float red_sq[16];

    int tid = threadIdx.x;
    if (tid < Ff) sv[tid] = v[tid];
    __syncthreads();

    int b  = blockIdx.x >> 5;          // 0..15
    int ng = blockIdx.x & 31;          // 0..31 (group of 64 n)
    int nl = tid & 63;                 // 0..63
    int fc = tid >> 6;                 // 0..7  (f-chunk of 16)
    int n  = ng * 64 + nl;

    const float* p  = emb + ((size_t)(b * Ff + fc * 16)) * Nn + n;
    const float* pv = sv + fc * 16;

    float s = 0.f, sum = 0.f, sq = 0.f;
#pragma unroll
    for (int f = 0; f < 16; f++) {
        float x = __ldg(p + (size_t)f * Nn);
        s   = fmaf(pv[f], x, s);
        sum += x;
        sq  = fmaf(x, x, sq);
    }
    spart[tid] = s;
    __syncthreads();
    if (tid < 64) {
        float tot = 0.f;
#pragma unroll
        for (int c = 0; c < 8; c++) tot += spart[c * 64 + tid];
        g_s[b * Nn + ng * 64 + tid] = tot;
    }

    // block reduce sum & sq -> plain per-block stores
    int lane = tid & 31;
    int wid  = tid >> 5;
#pragma unroll
    for (int o = 16; o > 0; o >>= 1) {
        sum += __shfl_xor_sync(0xffffffffu, sum, o);
        sq  += __shfl_xor_sync(0xffffffffu, sq, o);
    }
    if (lane == 0) { red_sum[wid] = sum; red_sq[wid] = sq; }
    __syncthreads();
    if (wid == 0) {
        float rs = (lane < 16) ? red_sum[lane] : 0.f;
        float rq = (lane < 16) ? red_sq[lane]  : 0.f;
#pragma unroll
        for (int o = 8; o > 0; o >>= 1) {
            rs += __shfl_xor_sync(0xffffffffu, rs, o);
            rq += __shfl_xor_sync(0xffffffffu, rq, o);
        }
        if (lane == 0) {
            g_psum[blockIdx.x] = rs;
            g_psq[blockIdx.x]  = rq;
        }
    }
}

// ---------------------------------------------------------------------------
// Pass 2 (fused finalize + output): each block redundantly reduces the 512
// L2-resident partials -> scale; computes E on the fly from g_s; writes
// out[b,i,j] = 1 / (1 + E_i*E_j) for 4 rows. 2 launches total (was 3) —
// each launch boundary costs ~2us of ramp, and k_exp was pure overhead.
// ---------------------------------------------------------------------------
__device__ __forceinline__ float frcp(float x) {
    float r;
    asm("rcp.approx.f32 %0, %1;" : "=f"(r) : "f"(x));
    return r;
}

__global__ void __launch_bounds__(512) k_main(const float* __restrict__ bias,
                                              float* __restrict__ out) {
    __shared__ float red_sum[16];
    __shared__ float red_sq[16];
    __shared__ float sh_scale, sh_hb;
    __shared__ float sh_p[4];

    int tid  = threadIdx.x;
    int lane = tid & 31;
    int wid  = tid >> 5;

    // reduce 512 partials (one per thread, L2-resident)
    float sum = g_psum[tid];
    float sq  = g_psq[tid];
#pragma unroll
    for (int o = 16; o > 0; o >>= 1) {
        sum += __shfl_xor_sync(0xffffffffu, sum, o);
        sq  += __shfl_xor_sync(0xffffffffu, sq, o);
    }
    if (lane == 0) { red_sum[wid] = sum; red_sq[wid] = sq; }
    __syncthreads();
    if (tid == 0) {
        double ds = 0.0, dq = 0.0;
#pragma unroll
        for (int w = 0; w < 16; w++) { ds += (double)red_sum[w]; dq += (double)red_sq[w]; }
        double m   = (double)TOT;
        double var = (dq - ds * ds / m) / (m - 1.0);
        sh_scale = (float)(1.0 / sqrt(var));
        sh_hb    = 0.5f * bias[0];
    }
    __syncthreads();

    int r0 = blockIdx.x << 2;          // first of 4 rows
    int b  = r0 >> 11;
    float scale = sh_scale;
    float hb    = sh_hb;

    if (tid < 4)
        sh_p[tid] = __expf(-fmaf(__ldg(g_s + r0 + tid), scale, hb));
    __syncthreads();

    float4 sj = __ldg((const float4*)(g_s + (size_t)b * Nn) + tid);
    float4 ej;
    ej.x = __expf(-fmaf(sj.x, scale, hb));
    ej.y = __expf(-fmaf(sj.y, scale, hb));
    ej.z = __expf(-fmaf(sj.z, scale, hb));
    ej.w = __expf(-fmaf(sj.w, scale, hb));

    float p0 = sh_p[0], p1 = sh_p[1], p2 = sh_p[2], p3 = sh_p[3];

    float4 o0, o1, o2, o3;
    o0.x = frcp(fmaf(p0, ej.x, 1.f)); o0.y = frcp(fmaf(p0, ej.y, 1.f));
    o0.z = frcp(fmaf(p0, ej.z, 1.f)); o0.w = frcp(fmaf(p0, ej.w, 1.f));
    o1.x = frcp(fmaf(p1, ej.x, 1.f)); o1.y = frcp(fmaf(p1, ej.y, 1.f));
    o1.z = frcp(fmaf(p1, ej.z, 1.f)); o1.w = frcp(fmaf(p1, ej.w, 1.f));
    o2.x = frcp(fmaf(p2, ej.x, 1.f)); o2.y = frcp(fmaf(p2, ej.y, 1.f));
    o2.z = frcp(fmaf(p2, ej.z, 1.f)); o2.w = frcp(fmaf(p2, ej.w, 1.f));
    o3.x = frcp(fmaf(p3, ej.x, 1.f)); o3.y = frcp(fmaf(p3, ej.y, 1.f));
    o3.z = frcp(fmaf(p3, ej.z, 1.f)); o3.w = frcp(fmaf(p3, ej.w, 1.f));

    float4* orow = (float4*)(out + (size_t)r0 * Nn) + tid;
    orow[0]          = o0;
    orow[Nn / 4]     = o1;
    orow[Nn / 2]     = o2;
    orow[3 * Nn / 4] = o3;
}

extern "C" void kernel_launch(void* const* d_in, const int* in_sizes, int n_in,
                              void* d_out, int out_size) {
    // inputs: adj_in [B,N,N] (unused), emb_in [B,F,N], v [F], b [1]
    const float* emb  = (const float*)d_in[1];
    const float* v    = (const float*)d_in[2];
    const float* bias = (const float*)d_in[3];
    float* out = (float*)d_out;

    k_fused<<<NBLK, 512>>>(emb, v);
    k_main<<<BN / 4, 512>>>(bias, out);
}

// round 12
// speedup vs baseline: 1.7937x; 1.7937x over previous
#include <cuda_runtime.h>
#include <cstdint>
#include <math.h>

#define Bb 16
#define Ff 128
#define Nn 2048
#define BN (Bb*Nn)          // 32768
#define TOT (Bb*Ff*Nn)      // 4194304
#define NBLK 512            // k_fused grid size

// scratch (allocation-free: __device__ globals)
__device__ float g_s[BN];
__device__ float g_psum[NBLK];
__device__ float g_psq[NBLK];
__device__ unsigned int g_count = 0;   // auto-wraps via atomicInc
__device__ float g_scale;
__device__ float g_hb;

// ---------------------------------------------------------------------------
// Pass 1: s[b,n] = sum_f v[f]*emb[b,f,n]; per-block partial sum/sumsq.
// Proven-fastest structure (R7): 512 threads = 8 fc (16 f) x 64 n. Grid 512.
// LAST block (threadfence+atomicInc pattern) reduces the 512 partials and
// computes g_scale/g_hb ONCE — replaces the k_exp launch.
// ---------------------------------------------------------------------------
__global__ void __launch_bounds__(512) k_fused(const float* __restrict__ emb,
                                               const float* __restrict__ v,
                                               const float* __restrict__ bias) {
    __shared__ float sv[Ff];
    __shared__ float spart[512];
    __shared__ float red_sum[16];
    __shared__ float red_sq[16];
    __shared__ bool  is_last;

    int tid = threadIdx.x;
    if (tid < Ff) sv[tid] = v[tid];
    __syncthreads();

    int b  = blockIdx.x >> 5;          // 0..15
    int ng = blockIdx.x & 31;          // 0..31 (group of 64 n)
    int nl = tid & 63;                 // 0..63
    int fc = tid >> 6;                 // 0..7  (f-chunk of 16)
    int n  = ng * 64 + nl;

    const float* p  = emb + ((size_t)(b * Ff + fc * 16)) * Nn + n;
    const float* pv = sv + fc * 16;

    float s = 0.f, sum = 0.f, sq = 0.f;
#pragma unroll
    for (int f = 0; f < 16; f++) {
        float x = __ldg(p + (size_t)f * Nn);
        s   = fmaf(pv[f], x, s);
        sum += x;
        sq  = fmaf(x, x, sq);
    }
    spart[tid] = s;
    __syncthreads();
    if (tid < 64) {
        float tot = 0.f;
#pragma unroll
        for (int c = 0; c < 8; c++) tot += spart[c * 64 + tid];
        g_s[b * Nn + ng * 64 + tid] = tot;
    }

    // block reduce sum & sq -> per-block partial stores
    int lane = tid & 31;
    int wid  = tid >> 5;
#pragma unroll
    for (int o = 16; o > 0; o >>= 1) {
        sum += __shfl_xor_sync(0xffffffffu, sum, o);
        sq  += __shfl_xor_sync(0xffffffffu, sq, o);
    }
    if (lane == 0) { red_sum[wid] = sum; red_sq[wid] = sq; }
    __syncthreads();
    if (wid == 0 && lane == 0) {
        float rs = 0.f, rq = 0.f;
#pragma unroll
        for (int w = 0; w < 16; w++) { rs += red_sum[w]; rq += red_sq[w]; }
        g_psum[blockIdx.x] = rs;
        g_psq[blockIdx.x]  = rq;
    }

    // last-block-done: reduce partials -> scale (computed exactly once)
    if (tid == 0) {
        __threadfence();
        unsigned int old = atomicInc(&g_count, NBLK - 1);  // wraps to 0
        is_last = (old == NBLK - 1);
    }
    __syncthreads();
    if (is_last) {
        float sum2 = g_psum[tid];
        float sq2  = g_psq[tid];
#pragma unroll
        for (int o = 16; o > 0; o >>= 1) {
            sum2 += __shfl_xor_sync(0xffffffffu, sum2, o);
            sq2  += __shfl_xor_sync(0xffffffffu, sq2, o);
        }
        if (lane == 0) { red_sum[wid] = sum2; red_sq[wid] = sq2; }
        __syncthreads();
        if (tid == 0) {
            double ds = 0.0, dq = 0.0;
#pragma unroll
            for (int w = 0; w < 16; w++) { ds += (double)red_sum[w]; dq += (double)red_sq[w]; }
            double m   = (double)TOT;
            double var = (dq - ds * ds / m) / (m - 1.0);
            g_scale = (float)(1.0 / sqrt(var));
            g_hb    = 0.5f * bias[0];
        }
    }
}

// ---------------------------------------------------------------------------
// Pass 2: out[b,i,j] = 1/(1 + E_i*E_j), E computed inline from g_s using the
// precomputed g_scale/g_hb (two scalar loads — NO per-block reduce/doubles,
// which is what sank R11). 4 rows per block, plain float4 stores (proven).
// ---------------------------------------------------------------------------
__device__ __forceinline__ float frcp(float x) {
    float r;
    asm("rcp.approx.f32 %0, %1;" : "=f"(r) : "f"(x));
    return r;
}

__global__ void __launch_bounds__(512) k_main(float* __restrict__ out) {
    __shared__ float sh_p[4];

    int tid = threadIdx.x;
    int r0  = blockIdx.x << 2;         // first of 4 rows
    int b   = r0 >> 11;

    float scale = g_scale;
    float hb    = g_hb;

    if (tid < 4)
        sh_p[tid] = __expf(-fmaf(__ldg(g_s + r0 + tid), scale, hb));
    __syncthreads();

    float4 sj = __ldg((const float4*)(g_s + (size_t)b * Nn) + tid);
    float4 ej;
    ej.x = __expf(-fmaf(sj.x, scale, hb));
    ej.y = __expf(-fmaf(sj.y, scale, hb));
    ej.z = __expf(-fmaf(sj.z, scale, hb));
    ej.w = __expf(-fmaf(sj.w, scale, hb));

    float p0 = sh_p[0], p1 = sh_p[1], p2 = sh_p[2], p3 = sh_p[3];

    float4 o0, o1, o2, o3;
    o0.x = frcp(fmaf(p0, ej.x, 1.f)); o0.y = frcp(fmaf(p0, ej.y, 1.f));
    o0.z = frcp(fmaf(p0, ej.z, 1.f)); o0.w = frcp(fmaf(p0, ej.w, 1.f));
    o1.x = frcp(fmaf(p1, ej.x, 1.f)); o1.y = frcp(fmaf(p1, ej.y, 1.f));
    o1.z = frcp(fmaf(p1, ej.z, 1.f)); o1.w = frcp(fmaf(p1, ej.w, 1.f));
    o2.x = frcp(fmaf(p2, ej.x, 1.f)); o2.y = frcp(fmaf(p2, ej.y, 1.f));
    o2.z = frcp(fmaf(p2, ej.z, 1.f)); o2.w = frcp(fmaf(p2, ej.w, 1.f));
    o3.x = frcp(fmaf(p3, ej.x, 1.f)); o3.y = frcp(fmaf(p3, ej.y, 1.f));
    o3.z = frcp(fmaf(p3, ej.z, 1.f)); o3.w = frcp(fmaf(p3, ej.w, 1.f));

    float4* orow = (float4*)(out + (size_t)r0 * Nn) + tid;
    orow[0]          = o0;
    orow[Nn / 4]     = o1;
    orow[Nn / 2]     = o2;
    orow[3 * Nn / 4] = o3;
}

extern "C" void kernel_launch(void* const* d_in, const int* in_sizes, int n_in,
                              void* d_out, int out_size) {
    // inputs: adj_in [B,N,N] (unused), emb_in [B,F,N], v [F], b [1]
    const float* emb  = (const float*)d_in[1];
    const float* v    = (const float*)d_in[2];
    const float* bias = (const float*)d_in[3];
    float* out = (float*)d_out;

    k_fused<<<NBLK, 512>>>(emb, v, bias);
    k_main<<<BN / 4, 512>>>(out);
}